// round 14
// baseline (speedup 1.0000x reference)
#include <cuda_runtime.h>
#include <cuda_fp16.h>
#include <cuda_bf16.h>
#include <cstdint>

#define MAX_N 50000
#define MAX_E 800000
#define IN_C  256
#define HID   128
#define OUTC  64
#define SCAN_B 256
#define SCAN_NBLK ((MAX_N + SCAN_B - 1) / SCAN_B)   // 196

// ---- scratch (device globals: no allocations allowed) ----
__device__ int    g_is64;
__device__ int    g_csr[MAX_E];
__device__ int    g_cnt[MAX_N];
__device__ int    g_start[MAX_N];
__device__ int    g_cursor[MAX_N];
__device__ int    g_bsum[SCAN_NBLK];
__device__ float  g_dis[MAX_N];
__device__ __half g_hs1[MAX_N * HID];   // UNSCALED layer-1 GEMM output (f16)
__device__ __half g_act1[MAX_N * HID];  // relu'd layer-1 output (f16)
__device__ __half g_hs2[MAX_N * OUTC];  // dis-scaled layer-2 GEMM output (f16)

// ---------------- CSR build ----------------
__global__ void k_zero_detect(const long long* __restrict__ ei, int n) {
    int i = blockIdx.x * blockDim.x + threadIdx.x;
    if (i < n) g_cnt[i] = 0;
    if (blockIdx.x == 0) {
        __shared__ int ok;
        if (threadIdx.x == 0) ok = 1;
        __syncthreads();
        long long v = ei[threadIdx.x];
        if (v < 0 || v >= MAX_N) ok = 0;
        __syncthreads();
        if (threadIdx.x == 0) g_is64 = ok;
    }
}

__global__ void k_hist(const void* __restrict__ ei, int E) {
    int i4 = (blockIdx.x * blockDim.x + threadIdx.x) * 4;
    if (i4 >= E) return;
    if (!g_is64 && i4 + 4 <= E) {
        int4 d = *reinterpret_cast<const int4*>((const int*)ei + E + i4);
        atomicAdd(&g_cnt[d.x], 1);
        atomicAdd(&g_cnt[d.y], 1);
        atomicAdd(&g_cnt[d.z], 1);
        atomicAdd(&g_cnt[d.w], 1);
    } else {
        for (int i = i4; i < min(i4 + 4, E); i++) {
            int d = g_is64 ? (int)((const long long*)ei)[i + E]
                           : ((const int*)ei)[i + E];
            atomicAdd(&g_cnt[d], 1);
        }
    }
}

__global__ void k_scan1(int n) {
    __shared__ int s[SCAN_B];
    int i = blockIdx.x * SCAN_B + threadIdx.x;
    int v = (i < n) ? g_cnt[i] : 0;
    s[threadIdx.x] = v;
    __syncthreads();
#pragma unroll
    for (int off = 1; off < SCAN_B; off <<= 1) {
        int x = (threadIdx.x >= off) ? s[threadIdx.x - off] : 0;
        __syncthreads();
        s[threadIdx.x] += x;
        __syncthreads();
    }
    if (i < n) g_start[i] = s[threadIdx.x] - v;
    if (threadIdx.x == SCAN_B - 1) g_bsum[blockIdx.x] = s[SCAN_B - 1];
}

__global__ void k_scan3(int n, int nblk) {
    __shared__ int s[SCAN_B];
    int v = (threadIdx.x < nblk) ? g_bsum[threadIdx.x] : 0;
    s[threadIdx.x] = v;
    __syncthreads();
#pragma unroll
    for (int off = 1; off < SCAN_B; off <<= 1) {
        int x = (threadIdx.x >= off) ? s[threadIdx.x - off] : 0;
        __syncthreads();
        s[threadIdx.x] += x;
        __syncthreads();
    }
    int boff = (blockIdx.x == 0) ? 0 : s[blockIdx.x - 1];
    int i = blockIdx.x * SCAN_B + threadIdx.x;
    if (i >= n) return;
    int st = g_start[i] + boff;
    g_start[i]  = st;
    g_cursor[i] = st;
    g_dis[i]    = rsqrtf((float)(g_cnt[i] + 1));
}

__global__ void k_fill(const void* __restrict__ ei, int E) {
    int i4 = (blockIdx.x * blockDim.x + threadIdx.x) * 4;
    if (i4 >= E) return;
    if (!g_is64 && i4 + 4 <= E) {
        int4 sv = *reinterpret_cast<const int4*>((const int*)ei + i4);
        int4 dv = *reinterpret_cast<const int4*>((const int*)ei + E + i4);
        g_csr[atomicAdd(&g_cursor[dv.x], 1)] = sv.x;
        g_csr[atomicAdd(&g_cursor[dv.y], 1)] = sv.y;
        g_csr[atomicAdd(&g_cursor[dv.z], 1)] = sv.z;
        g_csr[atomicAdd(&g_cursor[dv.w], 1)] = sv.w;
    } else {
        for (int i = i4; i < min(i4 + 4, E); i++) {
            int sIdx, d;
            if (g_is64) {
                const long long* p = (const long long*)ei;
                sIdx = (int)p[i]; d = (int)p[i + E];
            } else {
                const int* p = (const int*)ei;
                sIdx = p[i]; d = p[i + E];
            }
            g_csr[atomicAdd(&g_cursor[d], 1)] = sIdx;
        }
    }
}

// ---------------- 16-bit k16 tensor-core GEMM ----------------
__device__ __forceinline__ void mma16b(float* c, const unsigned* a, const unsigned* b) {
    asm volatile(
        "mma.sync.aligned.m16n8k16.row.col.f32.bf16.bf16.f32 "
        "{%0,%1,%2,%3},{%4,%5,%6,%7},{%8,%9},{%0,%1,%2,%3};"
        : "+f"(c[0]), "+f"(c[1]), "+f"(c[2]), "+f"(c[3])
        : "r"(a[0]), "r"(a[1]), "r"(a[2]), "r"(a[3]), "r"(b[0]), "r"(b[1]));
}

__device__ __forceinline__ void mma16h(float* c, const unsigned* a, const unsigned* b) {
    asm volatile(
        "mma.sync.aligned.m16n8k16.row.col.f32.f16.f16.f32 "
        "{%0,%1,%2,%3},{%4,%5,%6,%7},{%8,%9},{%0,%1,%2,%3};"
        : "+f"(c[0]), "+f"(c[1]), "+f"(c[2]), "+f"(c[3])
        : "r"(a[0]), "r"(a[1]), "r"(a[2]), "r"(a[3]), "r"(b[0]), "r"(b[1]));
}

__device__ __forceinline__ void split2_bf16(float e, float o, unsigned& hi, unsigned& lo) {
    __nv_bfloat16 he = __float2bfloat16_rn(e), ho = __float2bfloat16_rn(o);
    float re = e - __bfloat162float(he), ro = o - __bfloat162float(ho);
    __nv_bfloat162 h; h.x = he; h.y = ho;
    __nv_bfloat162 l = __floats2bfloat162_rn(re, ro);
    hi = *reinterpret_cast<unsigned*>(&h);
    lo = *reinterpret_cast<unsigned*>(&l);
}

__device__ __forceinline__ void split2_f16(float e, float o, unsigned& hi, unsigned& lo) {
    __half he = __float2half_rn(e), ho = __float2half_rn(o);
    float re = e - __half2float(he), ro = o - __half2float(ho);
    __half2 h; h.x = he; h.y = ho;
    __half2 l = __floats2half2_rn(re, ro);
    hi = *reinterpret_cast<unsigned*>(&h);
    lo = *reinterpret_cast<unsigned*>(&l);
}

template<int BN, bool SCALE, bool FP16A>
__global__ void __launch_bounds__(256)
gemm16(const void* __restrict__ Av, const float* __restrict__ W,
       __half* __restrict__ out, int M, int K)
{
    constexpr int BM = 128, BK = 16;
    constexpr int LDP = 12;
    constexpr int NF  = BN / 16;
    constexpr int B_PITER = BN / 32;

    __shared__ unsigned As_hi[BM * LDP];
    __shared__ unsigned As_lo[FP16A ? 1 : BM * LDP];
    __shared__ unsigned Bs_hi[BN * LDP], Bs_lo[BN * LDP];

    const int tid  = threadIdx.x;
    const int lane = tid & 31, warp = tid >> 5;
    const int wm = warp & 3, wn = warp >> 2;
    const int row0 = blockIdx.x * BM;

    float acc[2][NF][4] = {};

    uint4  ra_h;
    float4 ra_f0, ra_f1;
    float  rbe[B_PITER], rbo[B_PITER];

    auto loadTiles = [&](int kk) {
        if (FP16A) {
            const __half* A = (const __half*)Av;
            int r = tid >> 1, c = (tid & 1) * 8;
            ra_h = make_uint4(0, 0, 0, 0);
            if (row0 + r < M)
                ra_h = *reinterpret_cast<const uint4*>(A + (size_t)(row0 + r) * K + kk + c);
        } else {
            const float* A = (const float*)Av;
            int r = tid >> 2, c = (tid & 3) * 4;
            ra_f0 = make_float4(0.f, 0.f, 0.f, 0.f);
            ra_f1 = make_float4(0.f, 0.f, 0.f, 0.f);
            if (row0 + r < M)
                ra_f0 = *reinterpret_cast<const float4*>(A + (size_t)(row0 + r) * K + kk + c);
            if (row0 + r + 64 < M)
                ra_f1 = *reinterpret_cast<const float4*>(A + (size_t)(row0 + r + 64) * K + kk + c);
        }
#pragma unroll
        for (int i = 0; i < B_PITER; i++) {
            int idx = tid + i * 256;
            int kp = idx / BN, n = idx % BN;
            rbe[i] = W[(size_t)(kk + 2 * kp    ) * BN + n];
            rbo[i] = W[(size_t)(kk + 2 * kp + 1) * BN + n];
        }
    };

    auto storeTiles = [&]() {
        if (FP16A) {
            int r = tid >> 1, p0 = (tid & 1) * 4;
            As_hi[r*LDP + p0    ] = ra_h.x;
            As_hi[r*LDP + p0 + 1] = ra_h.y;
            As_hi[r*LDP + p0 + 2] = ra_h.z;
            As_hi[r*LDP + p0 + 3] = ra_h.w;
        } else {
            int r = tid >> 2, p0 = (tid & 3) * 2;
            unsigned h, l;
            split2_bf16(ra_f0.x, ra_f0.y, h, l); As_hi[r*LDP + p0    ] = h; As_lo[r*LDP + p0    ] = l;
            split2_bf16(ra_f0.z, ra_f0.w, h, l); As_hi[r*LDP + p0 + 1] = h; As_lo[r*LDP + p0 + 1] = l;
            int r1 = r + 64;
            split2_bf16(ra_f1.x, ra_f1.y, h, l); As_hi[r1*LDP + p0    ] = h; As_lo[r1*LDP + p0    ] = l;
            split2_bf16(ra_f1.z, ra_f1.w, h, l); As_hi[r1*LDP + p0 + 1] = h; As_lo[r1*LDP + p0 + 1] = l;
        }
#pragma unroll
        for (int i = 0; i < B_PITER; i++) {
            int idx = tid + i * 256;
            int kp = idx / BN, n = idx % BN;
            unsigned h, l;
            if (FP16A) split2_f16 (rbe[i], rbo[i], h, l);
            else       split2_bf16(rbe[i], rbo[i], h, l);
            Bs_hi[n*LDP + kp] = h;
            Bs_lo[n*LDP + kp] = l;
        }
    };

    auto compute = [&]() {
        unsigned ah[2][4], al[2][4];
        const int q = lane & 3;
#pragma unroll
        for (int mf = 0; mf < 2; mf++) {
            int r = wm * 32 + mf * 16 + (lane >> 2);
            ah[mf][0] = As_hi[ r      * LDP + q    ];
            ah[mf][1] = As_hi[(r + 8) * LDP + q    ];
            ah[mf][2] = As_hi[ r      * LDP + q + 4];
            ah[mf][3] = As_hi[(r + 8) * LDP + q + 4];
            if (!FP16A) {
                al[mf][0] = As_lo[ r      * LDP + q    ];
                al[mf][1] = As_lo[(r + 8) * LDP + q    ];
                al[mf][2] = As_lo[ r      * LDP + q + 4];
                al[mf][3] = As_lo[(r + 8) * LDP + q + 4];
            }
        }
#pragma unroll
        for (int nf = 0; nf < NF; nf++) {
            int n = wn * (BN / 2) + nf * 8 + (lane >> 2);
            unsigned bh[2], bl[2];
            bh[0] = Bs_hi[n*LDP + q];
            bh[1] = Bs_hi[n*LDP + q + 4];
            bl[0] = Bs_lo[n*LDP + q];
            bl[1] = Bs_lo[n*LDP + q + 4];
#pragma unroll
            for (int mf = 0; mf < 2; mf++) {
                if (FP16A) {
                    mma16h(acc[mf][nf], ah[mf], bh);
                    mma16h(acc[mf][nf], ah[mf], bl);
                } else {
                    mma16b(acc[mf][nf], ah[mf], bh);
                    mma16b(acc[mf][nf], ah[mf], bl);
                    mma16b(acc[mf][nf], al[mf], bh);
                }
            }
        }
    };

    loadTiles(0);
    storeTiles();
    __syncthreads();
    for (int kk = BK; kk < K; kk += BK) {
        loadTiles(kk);
        compute();
        __syncthreads();
        storeTiles();
        __syncthreads();
    }
    compute();

#pragma unroll
    for (int mf = 0; mf < 2; mf++) {
        int r0 = row0 + wm * 32 + mf * 16 + (lane >> 2);
        int r1 = r0 + 8;
        float d0 = 1.f, d1 = 1.f;
        if (SCALE) {
            d0 = (r0 < M) ? g_dis[r0] : 0.f;
            d1 = (r1 < M) ? g_dis[r1] : 0.f;
        }
#pragma unroll
        for (int nf = 0; nf < NF; nf++) {
            int c = wn * (BN / 2) + nf * 8 + (lane & 3) * 2;
            if (r0 < M)
                *reinterpret_cast<__half2*>(out + (size_t)r0 * BN + c) =
                    __floats2half2_rn(acc[mf][nf][0] * d0, acc[mf][nf][1] * d0);
            if (r1 < M)
                *reinterpret_cast<__half2*>(out + (size_t)r1 * BN + c) =
                    __floats2half2_rn(acc[mf][nf][2] * d1, acc[mf][nf][3] * d1);
        }
    }
}

// ---------------- gather aggregation (R11 data path + shfl index broadcast) ----------------
__device__ __forceinline__ void acch(float* a, uint2 v, float s) {
    __half2 h0 = *reinterpret_cast<__half2*>(&v.x);
    __half2 h1 = *reinterpret_cast<__half2*>(&v.y);
    float2 f0 = __half22float2(h0), f1 = __half22float2(h1);
    a[0] = fmaf(s, f0.x, a[0]);
    a[1] = fmaf(s, f0.y, a[1]);
    a[2] = fmaf(s, f1.x, a[2]);
    a[3] = fmaf(s, f1.y, a[3]);
}

__device__ __forceinline__ void acch2(float* a, unsigned v, float s) {
    float2 f = __half22float2(*reinterpret_cast<__half2*>(&v));
    a[0] = fmaf(s, f.x, a[0]);
    a[1] = fmaf(s, f.y, a[1]);
}

// layer 1: one warp per node, 8B per lane. Indices + dis fetched once per
// 32-edge chunk via ONE coalesced load each, broadcast by shfl.
__global__ void k_agg128(const __half* __restrict__ hs, __half* __restrict__ out,
                         const float* __restrict__ bias, int N)
{
    int w = (blockIdx.x * blockDim.x + threadIdx.x) >> 5;
    if (w >= N) return;
    int lane = threadIdx.x & 31;
    const uint2* base = (const uint2*)hs;

    int beg = g_start[w], cnt = g_cnt[w];
    float dw = g_dis[w];
    float a[4] = {0.f, 0.f, 0.f, 0.f};
    acch(a, base[(size_t)w * 32 + lane], dw);   // self loop

    for (int c0 = 0; c0 < cnt; c0 += 32) {
        int m = min(32, cnt - c0);
        int   idx = (lane < m) ? g_csr[beg + c0 + lane] : 0;   // 1 coalesced load
        float dv  = (lane < m) ? g_dis[idx] : 0.f;             // 1 gathered load
        int j = 0;
        for (; j + 4 <= m; j += 4) {
            int s0 = __shfl_sync(0xFFFFFFFFu, idx, j    );
            int s1 = __shfl_sync(0xFFFFFFFFu, idx, j + 1);
            int s2 = __shfl_sync(0xFFFFFFFFu, idx, j + 2);
            int s3 = __shfl_sync(0xFFFFFFFFu, idx, j + 3);
            float d0 = __shfl_sync(0xFFFFFFFFu, dv, j    );
            float d1 = __shfl_sync(0xFFFFFFFFu, dv, j + 1);
            float d2 = __shfl_sync(0xFFFFFFFFu, dv, j + 2);
            float d3 = __shfl_sync(0xFFFFFFFFu, dv, j + 3);
            uint2 v0 = base[(size_t)s0 * 32 + lane];
            uint2 v1 = base[(size_t)s1 * 32 + lane];
            uint2 v2 = base[(size_t)s2 * 32 + lane];
            uint2 v3 = base[(size_t)s3 * 32 + lane];
            acch(a, v0, d0); acch(a, v1, d1);
            acch(a, v2, d2); acch(a, v3, d3);
        }
        for (; j < m; j++) {
            int   s = __shfl_sync(0xFFFFFFFFu, idx, j);
            float d = __shfl_sync(0xFFFFFFFFu, dv,  j);
            acch(a, base[(size_t)s * 32 + lane], d);
        }
    }

    float4 b = ((const float4*)bias)[lane];
    uint2 r;
    __half2 r0 = __floats2half2_rn(fmaxf(fmaf(dw, a[0], b.x), 0.f),
                                   fmaxf(fmaf(dw, a[1], b.y), 0.f));
    __half2 r1 = __floats2half2_rn(fmaxf(fmaf(dw, a[2], b.z), 0.f),
                                   fmaxf(fmaf(dw, a[3], b.w), 0.f));
    r.x = *reinterpret_cast<unsigned*>(&r0);
    r.y = *reinterpret_cast<unsigned*>(&r1);
    ((uint2*)out)[(size_t)w * 32 + lane] = r;
}

// layer 2: one warp per node, 4B (half2) per lane, same shfl index scheme
__global__ void k_agg64(const __half* __restrict__ hs, float* __restrict__ out,
                        const float* __restrict__ bias, int N)
{
    int node = (blockIdx.x * blockDim.x + threadIdx.x) >> 5;
    if (node >= N) return;
    int lane = threadIdx.x & 31;
    const unsigned* base = (const unsigned*)hs;

    int beg = g_start[node], cnt = g_cnt[node];
    float a[2] = {0.f, 0.f};
    acch2(a, base[(size_t)node * 32 + lane], 1.f);   // self loop (already scaled)

    for (int c0 = 0; c0 < cnt; c0 += 32) {
        int m = min(32, cnt - c0);
        int idx = (lane < m) ? g_csr[beg + c0 + lane] : 0;   // 1 coalesced load
        int j = 0;
        for (; j + 4 <= m; j += 4) {
            int s0 = __shfl_sync(0xFFFFFFFFu, idx, j    );
            int s1 = __shfl_sync(0xFFFFFFFFu, idx, j + 1);
            int s2 = __shfl_sync(0xFFFFFFFFu, idx, j + 2);
            int s3 = __shfl_sync(0xFFFFFFFFu, idx, j + 3);
            unsigned v0 = base[(size_t)s0 * 32 + lane];
            unsigned v1 = base[(size_t)s1 * 32 + lane];
            unsigned v2 = base[(size_t)s2 * 32 + lane];
            unsigned v3 = base[(size_t)s3 * 32 + lane];
            acch2(a, v0, 1.f); acch2(a, v1, 1.f);
            acch2(a, v2, 1.f); acch2(a, v3, 1.f);
        }
        for (; j < m; j++) {
            int s = __shfl_sync(0xFFFFFFFFu, idx, j);
            acch2(a, base[(size_t)s * 32 + lane], 1.f);
        }
    }

    float dw = g_dis[node];
    float2 b = ((const float2*)bias)[lane];
    float2 r;
    r.x = fmaf(dw, a[0], b.x);
    r.y = fmaf(dw, a[1], b.y);
    ((float2*)out)[(size_t)node * 32 + lane] = r;
}

// ---------------- launch (exact R11 structure) ----------------
extern "C" void kernel_launch(void* const* d_in, const int* in_sizes, int n_in,
                              void* d_out, int out_size)
{
    const float* x   = (const float*)d_in[0];
    const void*  ei  = d_in[1];
    const float* W1  = (const float*)d_in[2];
    const float* b1  = (const float*)d_in[3];
    const float* W2  = (const float*)d_in[4];
    const float* b2  = (const float*)d_in[5];
    float*       out = (float*)d_out;

    const int N = in_sizes[0] / IN_C;   // 50000
    const int E = in_sizes[1] / 2;      // 800000
    const int nscan = (N + SCAN_B - 1) / SCAN_B;
    const int e4blocks = ((E + 3) / 4 + 255) / 256;

    __half *p_hs1, *p_act1, *p_hs2;
    cudaGetSymbolAddress((void**)&p_hs1,  g_hs1);
    cudaGetSymbolAddress((void**)&p_act1, g_act1);
    cudaGetSymbolAddress((void**)&p_hs2,  g_hs2);

    static cudaStream_t s2 = nullptr;
    static cudaEvent_t evFork = nullptr, evJoin = nullptr;
    if (!s2) {
        if (cudaStreamCreateWithFlags(&s2, cudaStreamNonBlocking) != cudaSuccess) s2 = nullptr;
        if (s2) {
            cudaEventCreateWithFlags(&evFork, cudaEventDisableTiming);
            cudaEventCreateWithFlags(&evJoin, cudaEventDisableTiming);
        }
    }

    // ---- fork: GEMM1 (split-bf16) on side stream, overlapping CSR build ----
    bool forked = false;
    if (s2) {
        cudaEventRecord(evFork, 0);
        cudaStreamWaitEvent(s2, evFork, 0);
        gemm16<HID, false, false><<<(N + 127) / 128, 256, 0, s2>>>(x, W1, p_hs1, N, IN_C);
        cudaEventRecord(evJoin, s2);
        forked = true;
    }

    // ---- main stream: CSR build + dis ----
    k_zero_detect<<<(N + 255) / 256, 256>>>((const long long*)ei, N);
    k_hist<<<e4blocks, 256>>>(ei, E);
    k_scan1<<<nscan, SCAN_B>>>(N);
    k_scan3<<<nscan, SCAN_B>>>(N, nscan);
    k_fill<<<e4blocks, 256>>>(ei, E);

    if (forked) cudaStreamWaitEvent(0, evJoin, 0);
    else        gemm16<HID, false, false><<<(N + 127) / 128, 256>>>(x, W1, p_hs1, N, IN_C);

    // ---- layer 1 aggregate (+dis both sides, bias, relu) -> f16 act1 ----
    k_agg128<<<(N * 32 + 255) / 256, 256>>>(p_hs1, p_act1, b1, N);

    // ---- layer 2 GEMM (f16 A exact, W2 f16-split, dis-scaled) + aggregate ----
    gemm16<OUTC, true, true><<<(N + 127) / 128, 256>>>(p_act1, W2, p_hs2, N, HID);
    k_agg64<<<(N * 32 + 255) / 256, 256>>>(p_hs2, out, b2, N);
}

// round 15
// speedup vs baseline: 1.1144x; 1.1144x over previous
#include <cuda_runtime.h>
#include <cuda_fp16.h>
#include <cuda_bf16.h>
#include <cstdint>

#define MAX_N 50000
#define MAX_E 800000
#define IN_C  256
#define HID   128
#define OUTC  64
#define SCAN_B 256
#define SCAN_NBLK ((MAX_N + SCAN_B - 1) / SCAN_B)   // 196

// ---- scratch (device globals: no allocations allowed) ----
__device__ int    g_is64;
__device__ int    g_csr[MAX_E];
__device__ int    g_cnt[MAX_N];
__device__ int    g_start[MAX_N];
__device__ int    g_cursor[MAX_N];
__device__ int    g_bsum[SCAN_NBLK];
__device__ float  g_dis[MAX_N];
__device__ __half g_hs1[MAX_N * HID];   // UNSCALED layer-1 GEMM output (f16)
__device__ __half g_act1[MAX_N * HID];  // relu'd layer-1 output (f16)
__device__ __half g_hs2[MAX_N * OUTC];  // dis-scaled layer-2 GEMM output (f16)

// ---------------- CSR build ----------------
__global__ void k_detect(const long long* __restrict__ ei) {
    __shared__ int ok;
    if (threadIdx.x == 0) ok = 1;
    __syncthreads();
    long long v = ei[threadIdx.x];
    if (v < 0 || v >= MAX_N) ok = 0;
    __syncthreads();
    if (threadIdx.x == 0) g_is64 = ok;
}

__global__ void k_hist(const void* __restrict__ ei, int E) {
    int i4 = (blockIdx.x * blockDim.x + threadIdx.x) * 4;
    if (i4 >= E) return;
    if (!g_is64 && i4 + 4 <= E) {
        int4 d = *reinterpret_cast<const int4*>((const int*)ei + E + i4);
        atomicAdd(&g_cnt[d.x], 1);
        atomicAdd(&g_cnt[d.y], 1);
        atomicAdd(&g_cnt[d.z], 1);
        atomicAdd(&g_cnt[d.w], 1);
    } else {
        for (int i = i4; i < min(i4 + 4, E); i++) {
            int d = g_is64 ? (int)((const long long*)ei)[i + E]
                           : ((const int*)ei)[i + E];
            atomicAdd(&g_cnt[d], 1);
        }
    }
}

__global__ void k_scan1(int n) {
    __shared__ int s[SCAN_B];
    int i = blockIdx.x * SCAN_B + threadIdx.x;
    int v = (i < n) ? g_cnt[i] : 0;
    s[threadIdx.x] = v;
    __syncthreads();
#pragma unroll
    for (int off = 1; off < SCAN_B; off <<= 1) {
        int x = (threadIdx.x >= off) ? s[threadIdx.x - off] : 0;
        __syncthreads();
        s[threadIdx.x] += x;
        __syncthreads();
    }
    if (i < n) g_start[i] = s[threadIdx.x] - v;
    if (threadIdx.x == SCAN_B - 1) g_bsum[blockIdx.x] = s[SCAN_B - 1];
}

// scan2 folded in: every block redundantly scans the 196 block sums in smem
__global__ void k_scan3(int n, int nblk) {
    __shared__ int s[SCAN_B];
    int v = (threadIdx.x < nblk) ? g_bsum[threadIdx.x] : 0;
    s[threadIdx.x] = v;
    __syncthreads();
#pragma unroll
    for (int off = 1; off < SCAN_B; off <<= 1) {
        int x = (threadIdx.x >= off) ? s[threadIdx.x - off] : 0;
        __syncthreads();
        s[threadIdx.x] += x;
        __syncthreads();
    }
    int boff = (blockIdx.x == 0) ? 0 : s[blockIdx.x - 1];
    int i = blockIdx.x * SCAN_B + threadIdx.x;
    if (i >= n) return;
    int st = g_start[i] + boff;
    g_start[i]  = st;
    g_cursor[i] = st;
    g_dis[i]    = rsqrtf((float)(g_cnt[i] + 1));
}

__global__ void k_fill(const void* __restrict__ ei, int E) {
    int i4 = (blockIdx.x * blockDim.x + threadIdx.x) * 4;
    if (i4 >= E) return;
    if (!g_is64 && i4 + 4 <= E) {
        int4 sv = *reinterpret_cast<const int4*>((const int*)ei + i4);
        int4 dv = *reinterpret_cast<const int4*>((const int*)ei + E + i4);
        g_csr[atomicAdd(&g_cursor[dv.x], 1)] = sv.x;
        g_csr[atomicAdd(&g_cursor[dv.y], 1)] = sv.y;
        g_csr[atomicAdd(&g_cursor[dv.z], 1)] = sv.z;
        g_csr[atomicAdd(&g_cursor[dv.w], 1)] = sv.w;
    } else {
        for (int i = i4; i < min(i4 + 4, E); i++) {
            int sIdx, d;
            if (g_is64) {
                const long long* p = (const long long*)ei;
                sIdx = (int)p[i]; d = (int)p[i + E];
            } else {
                const int* p = (const int*)ei;
                sIdx = p[i]; d = p[i + E];
            }
            g_csr[atomicAdd(&g_cursor[d], 1)] = sIdx;
        }
    }
}

// ---------------- 16-bit k16 tensor-core GEMM ----------------
__device__ __forceinline__ void mma16b(float* c, const unsigned* a, const unsigned* b) {
    asm volatile(
        "mma.sync.aligned.m16n8k16.row.col.f32.bf16.bf16.f32 "
        "{%0,%1,%2,%3},{%4,%5,%6,%7},{%8,%9},{%0,%1,%2,%3};"
        : "+f"(c[0]), "+f"(c[1]), "+f"(c[2]), "+f"(c[3])
        : "r"(a[0]), "r"(a[1]), "r"(a[2]), "r"(a[3]), "r"(b[0]), "r"(b[1]));
}

__device__ __forceinline__ void mma16h(float* c, const unsigned* a, const unsigned* b) {
    asm volatile(
        "mma.sync.aligned.m16n8k16.row.col.f32.f16.f16.f32 "
        "{%0,%1,%2,%3},{%4,%5,%6,%7},{%8,%9},{%0,%1,%2,%3};"
        : "+f"(c[0]), "+f"(c[1]), "+f"(c[2]), "+f"(c[3])
        : "r"(a[0]), "r"(a[1]), "r"(a[2]), "r"(a[3]), "r"(b[0]), "r"(b[1]));
}

__device__ __forceinline__ void split2_bf16(float e, float o, unsigned& hi, unsigned& lo) {
    __nv_bfloat16 he = __float2bfloat16_rn(e), ho = __float2bfloat16_rn(o);
    float re = e - __bfloat162float(he), ro = o - __bfloat162float(ho);
    __nv_bfloat162 h; h.x = he; h.y = ho;
    __nv_bfloat162 l = __floats2bfloat162_rn(re, ro);
    hi = *reinterpret_cast<unsigned*>(&h);
    lo = *reinterpret_cast<unsigned*>(&l);
}

__device__ __forceinline__ void split2_f16(float e, float o, unsigned& hi, unsigned& lo) {
    __half he = __float2half_rn(e), ho = __float2half_rn(o);
    float re = e - __half2float(he), ro = o - __half2float(ho);
    __half2 h; h.x = he; h.y = ho;
    __half2 l = __floats2half2_rn(re, ro);
    hi = *reinterpret_cast<unsigned*>(&h);
    lo = *reinterpret_cast<unsigned*>(&l);
}

template<int BN, bool SCALE, bool FP16A>
__global__ void __launch_bounds__(256)
gemm16(const void* __restrict__ Av, const float* __restrict__ W,
       __half* __restrict__ out, int M, int K)
{
    constexpr int BM = 128, BK = 16;
    constexpr int LDP = 12;
    constexpr int NF  = BN / 16;
    constexpr int B_PITER = BN / 32;

    __shared__ unsigned As_hi[BM * LDP];
    __shared__ unsigned As_lo[FP16A ? 1 : BM * LDP];
    __shared__ unsigned Bs_hi[BN * LDP], Bs_lo[BN * LDP];

    const int tid  = threadIdx.x;
    const int lane = tid & 31, warp = tid >> 5;
    const int wm = warp & 3, wn = warp >> 2;
    const int row0 = blockIdx.x * BM;

    float acc[2][NF][4] = {};

    uint4  ra_h;
    float4 ra_f0, ra_f1;
    float  rbe[B_PITER], rbo[B_PITER];

    auto loadTiles = [&](int kk) {
        if (FP16A) {
            const __half* A = (const __half*)Av;
            int r = tid >> 1, c = (tid & 1) * 8;
            ra_h = make_uint4(0, 0, 0, 0);
            if (row0 + r < M)
                ra_h = *reinterpret_cast<const uint4*>(A + (size_t)(row0 + r) * K + kk + c);
        } else {
            const float* A = (const float*)Av;
            int r = tid >> 2, c = (tid & 3) * 4;
            ra_f0 = make_float4(0.f, 0.f, 0.f, 0.f);
            ra_f1 = make_float4(0.f, 0.f, 0.f, 0.f);
            if (row0 + r < M)
                ra_f0 = *reinterpret_cast<const float4*>(A + (size_t)(row0 + r) * K + kk + c);
            if (row0 + r + 64 < M)
                ra_f1 = *reinterpret_cast<const float4*>(A + (size_t)(row0 + r + 64) * K + kk + c);
        }
#pragma unroll
        for (int i = 0; i < B_PITER; i++) {
            int idx = tid + i * 256;
            int kp = idx / BN, n = idx % BN;
            rbe[i] = W[(size_t)(kk + 2 * kp    ) * BN + n];
            rbo[i] = W[(size_t)(kk + 2 * kp + 1) * BN + n];
        }
    };

    auto storeTiles = [&]() {
        if (FP16A) {
            int r = tid >> 1, p0 = (tid & 1) * 4;
            As_hi[r*LDP + p0    ] = ra_h.x;
            As_hi[r*LDP + p0 + 1] = ra_h.y;
            As_hi[r*LDP + p0 + 2] = ra_h.z;
            As_hi[r*LDP + p0 + 3] = ra_h.w;
        } else {
            int r = tid >> 2, p0 = (tid & 3) * 2;
            unsigned h, l;
            split2_bf16(ra_f0.x, ra_f0.y, h, l); As_hi[r*LDP + p0    ] = h; As_lo[r*LDP + p0    ] = l;
            split2_bf16(ra_f0.z, ra_f0.w, h, l); As_hi[r*LDP + p0 + 1] = h; As_lo[r*LDP + p0 + 1] = l;
            int r1 = r + 64;
            split2_bf16(ra_f1.x, ra_f1.y, h, l); As_hi[r1*LDP + p0    ] = h; As_lo[r1*LDP + p0    ] = l;
            split2_bf16(ra_f1.z, ra_f1.w, h, l); As_hi[r1*LDP + p0 + 1] = h; As_lo[r1*LDP + p0 + 1] = l;
        }
#pragma unroll
        for (int i = 0; i < B_PITER; i++) {
            int idx = tid + i * 256;
            int kp = idx / BN, n = idx % BN;
            unsigned h, l;
            if (FP16A) split2_f16 (rbe[i], rbo[i], h, l);
            else       split2_bf16(rbe[i], rbo[i], h, l);
            Bs_hi[n*LDP + kp] = h;
            Bs_lo[n*LDP + kp] = l;
        }
    };

    auto compute = [&]() {
        unsigned ah[2][4], al[2][4];
        const int q = lane & 3;
#pragma unroll
        for (int mf = 0; mf < 2; mf++) {
            int r = wm * 32 + mf * 16 + (lane >> 2);
            ah[mf][0] = As_hi[ r      * LDP + q    ];
            ah[mf][1] = As_hi[(r + 8) * LDP + q    ];
            ah[mf][2] = As_hi[ r      * LDP + q + 4];
            ah[mf][3] = As_hi[(r + 8) * LDP + q + 4];
            if (!FP16A) {
                al[mf][0] = As_lo[ r      * LDP + q    ];
                al[mf][1] = As_lo[(r + 8) * LDP + q    ];
                al[mf][2] = As_lo[ r      * LDP + q + 4];
                al[mf][3] = As_lo[(r + 8) * LDP + q + 4];
            }
        }
#pragma unroll
        for (int nf = 0; nf < NF; nf++) {
            int n = wn * (BN / 2) + nf * 8 + (lane >> 2);
            unsigned bh[2], bl[2];
            bh[0] = Bs_hi[n*LDP + q];
            bh[1] = Bs_hi[n*LDP + q + 4];
            bl[0] = Bs_lo[n*LDP + q];
            bl[1] = Bs_lo[n*LDP + q + 4];
#pragma unroll
            for (int mf = 0; mf < 2; mf++) {
                if (FP16A) {
                    mma16h(acc[mf][nf], ah[mf], bh);
                    mma16h(acc[mf][nf], ah[mf], bl);
                } else {
                    mma16b(acc[mf][nf], ah[mf], bh);
                    mma16b(acc[mf][nf], ah[mf], bl);
                    mma16b(acc[mf][nf], al[mf], bh);
                }
            }
        }
    };

    loadTiles(0);
    storeTiles();
    __syncthreads();
    for (int kk = BK; kk < K; kk += BK) {
        loadTiles(kk);
        compute();
        __syncthreads();
        storeTiles();
        __syncthreads();
    }
    compute();

#pragma unroll
    for (int mf = 0; mf < 2; mf++) {
        int r0 = row0 + wm * 32 + mf * 16 + (lane >> 2);
        int r1 = r0 + 8;
        float d0 = 1.f, d1 = 1.f;
        if (SCALE) {
            d0 = (r0 < M) ? g_dis[r0] : 0.f;
            d1 = (r1 < M) ? g_dis[r1] : 0.f;
        }
#pragma unroll
        for (int nf = 0; nf < NF; nf++) {
            int c = wn * (BN / 2) + nf * 8 + (lane & 3) * 2;
            if (r0 < M)
                *reinterpret_cast<__half2*>(out + (size_t)r0 * BN + c) =
                    __floats2half2_rn(acc[mf][nf][0] * d0, acc[mf][nf][1] * d0);
            if (r1 < M)
                *reinterpret_cast<__half2*>(out + (size_t)r1 * BN + c) =
                    __floats2half2_rn(acc[mf][nf][2] * d1, acc[mf][nf][3] * d1);
        }
    }
}

// ---------------- gather aggregation (R11 proven shapes — FROZEN) ----------------
__device__ __forceinline__ void acch(float* a, uint2 v, float s) {
    __half2 h0 = *reinterpret_cast<__half2*>(&v.x);
    __half2 h1 = *reinterpret_cast<__half2*>(&v.y);
    float2 f0 = __half22float2(h0), f1 = __half22float2(h1);
    a[0] = fmaf(s, f0.x, a[0]);
    a[1] = fmaf(s, f0.y, a[1]);
    a[2] = fmaf(s, f1.x, a[2]);
    a[3] = fmaf(s, f1.y, a[3]);
}

__device__ __forceinline__ void acch2(float* a, unsigned v, float s) {
    float2 f = __half22float2(*reinterpret_cast<__half2*>(&v));
    a[0] = fmaf(s, f.x, a[0]);
    a[1] = fmaf(s, f.y, a[1]);
}

// layer 1: one warp per node, 8B per lane
__global__ void k_agg128(const __half* __restrict__ hs, __half* __restrict__ out,
                         const float* __restrict__ bias, int N)
{
    int w = (blockIdx.x * blockDim.x + threadIdx.x) >> 5;
    if (w >= N) return;
    int lane = threadIdx.x & 31;
    const uint2* base = (const uint2*)hs;

    int beg = g_start[w], cnt = g_cnt[w];
    float dw = g_dis[w];
    float a[4] = {0.f, 0.f, 0.f, 0.f};
    acch(a, base[(size_t)w * 32 + lane], dw);   // self loop

    int e = 0;
    for (; e + 8 <= cnt; e += 8) {
        int s0 = g_csr[beg+e  ], s1 = g_csr[beg+e+1], s2 = g_csr[beg+e+2], s3 = g_csr[beg+e+3];
        int s4 = g_csr[beg+e+4], s5 = g_csr[beg+e+5], s6 = g_csr[beg+e+6], s7 = g_csr[beg+e+7];
        uint2 v0 = base[(size_t)s0*32+lane], v1 = base[(size_t)s1*32+lane];
        uint2 v2 = base[(size_t)s2*32+lane], v3 = base[(size_t)s3*32+lane];
        uint2 v4 = base[(size_t)s4*32+lane], v5 = base[(size_t)s5*32+lane];
        uint2 v6 = base[(size_t)s6*32+lane], v7 = base[(size_t)s7*32+lane];
        acch(a, v0, g_dis[s0]); acch(a, v1, g_dis[s1]);
        acch(a, v2, g_dis[s2]); acch(a, v3, g_dis[s3]);
        acch(a, v4, g_dis[s4]); acch(a, v5, g_dis[s5]);
        acch(a, v6, g_dis[s6]); acch(a, v7, g_dis[s7]);
    }
    for (; e < cnt; e++) {
        int s = g_csr[beg + e];
        acch(a, base[(size_t)s*32+lane], g_dis[s]);
    }

    float4 b = ((const float4*)bias)[lane];
    uint2 r;
    __half2 r0 = __floats2half2_rn(fmaxf(fmaf(dw, a[0], b.x), 0.f),
                                   fmaxf(fmaf(dw, a[1], b.y), 0.f));
    __half2 r1 = __floats2half2_rn(fmaxf(fmaf(dw, a[2], b.z), 0.f),
                                   fmaxf(fmaf(dw, a[3], b.w), 0.f));
    r.x = *reinterpret_cast<unsigned*>(&r0);
    r.y = *reinterpret_cast<unsigned*>(&r1);
    ((uint2*)out)[(size_t)w * 32 + lane] = r;
}

// layer 2: one warp per node, 4B (half2) per lane
__global__ void k_agg64(const __half* __restrict__ hs, float* __restrict__ out,
                        const float* __restrict__ bias, int N)
{
    int node = (blockIdx.x * blockDim.x + threadIdx.x) >> 5;
    if (node >= N) return;
    int lane = threadIdx.x & 31;
    const unsigned* base = (const unsigned*)hs;

    int beg = g_start[node], cnt = g_cnt[node];
    float a[2] = {0.f, 0.f};
    acch2(a, base[(size_t)node * 32 + lane], 1.f);   // self loop (already scaled)

    int e = 0;
    for (; e + 8 <= cnt; e += 8) {
        int s0 = g_csr[beg+e  ], s1 = g_csr[beg+e+1], s2 = g_csr[beg+e+2], s3 = g_csr[beg+e+3];
        int s4 = g_csr[beg+e+4], s5 = g_csr[beg+e+5], s6 = g_csr[beg+e+6], s7 = g_csr[beg+e+7];
        unsigned v0 = base[(size_t)s0*32+lane], v1 = base[(size_t)s1*32+lane];
        unsigned v2 = base[(size_t)s2*32+lane], v3 = base[(size_t)s3*32+lane];
        unsigned v4 = base[(size_t)s4*32+lane], v5 = base[(size_t)s5*32+lane];
        unsigned v6 = base[(size_t)s6*32+lane], v7 = base[(size_t)s7*32+lane];
        acch2(a, v0, 1.f); acch2(a, v1, 1.f); acch2(a, v2, 1.f); acch2(a, v3, 1.f);
        acch2(a, v4, 1.f); acch2(a, v5, 1.f); acch2(a, v6, 1.f); acch2(a, v7, 1.f);
    }
    for (; e < cnt; e++)
        acch2(a, base[(size_t)g_csr[beg+e]*32+lane], 1.f);

    float dw = g_dis[node];
    float2 b = ((const float2*)bias)[lane];
    float2 r;
    r.x = fmaf(dw, a[0], b.x);
    r.y = fmaf(dw, a[1], b.y);
    ((float2*)out)[(size_t)node * 32 + lane] = r;
}

// ---------------- launch (R11 structure; memset replaces zero kernel) ----------------
extern "C" void kernel_launch(void* const* d_in, const int* in_sizes, int n_in,
                              void* d_out, int out_size)
{
    const float* x   = (const float*)d_in[0];
    const void*  ei  = d_in[1];
    const float* W1  = (const float*)d_in[2];
    const float* b1  = (const float*)d_in[3];
    const float* W2  = (const float*)d_in[4];
    const float* b2  = (const float*)d_in[5];
    float*       out = (float*)d_out;

    const int N = in_sizes[0] / IN_C;   // 50000
    const int E = in_sizes[1] / 2;      // 800000
    const int nscan = (N + SCAN_B - 1) / SCAN_B;
    const int e4blocks = ((E + 3) / 4 + 255) / 256;

    __half *p_hs1, *p_act1, *p_hs2;
    int    *p_cnt;
    cudaGetSymbolAddress((void**)&p_hs1,  g_hs1);
    cudaGetSymbolAddress((void**)&p_act1, g_act1);
    cudaGetSymbolAddress((void**)&p_hs2,  g_hs2);
    cudaGetSymbolAddress((void**)&p_cnt,  g_cnt);

    static cudaStream_t s2 = nullptr;
    static cudaEvent_t evFork = nullptr, evJoin = nullptr;
    if (!s2) {
        if (cudaStreamCreateWithFlags(&s2, cudaStreamNonBlocking) != cudaSuccess) s2 = nullptr;
        if (s2) {
            cudaEventCreateWithFlags(&evFork, cudaEventDisableTiming);
            cudaEventCreateWithFlags(&evJoin, cudaEventDisableTiming);
        }
    }

    // ---- fork: GEMM1 (split-bf16) on side stream, overlapping CSR build ----
    bool forked = false;
    if (s2) {
        cudaEventRecord(evFork, 0);
        cudaStreamWaitEvent(s2, evFork, 0);
        gemm16<HID, false, false><<<(N + 127) / 128, 256, 0, s2>>>(x, W1, p_hs1, N, IN_C);
        cudaEventRecord(evJoin, s2);
        forked = true;
    }

    // ---- main stream: CSR build + dis ----
    cudaMemsetAsync(p_cnt, 0, (size_t)N * sizeof(int), 0);   // DMA-path zeroing
    k_detect<<<1, 256>>>((const long long*)ei);
    k_hist<<<e4blocks, 256>>>(ei, E);
    k_scan1<<<nscan, SCAN_B>>>(N);
    k_scan3<<<nscan, SCAN_B>>>(N, nscan);
    k_fill<<<e4blocks, 256>>>(ei, E);

    if (forked) cudaStreamWaitEvent(0, evJoin, 0);
    else        gemm16<HID, false, false><<<(N + 127) / 128, 256>>>(x, W1, p_hs1, N, IN_C);

    // ---- layer 1 aggregate (+dis both sides, bias, relu) -> f16 act1 ----
    k_agg128<<<(N * 32 + 255) / 256, 256>>>(p_hs1, p_act1, b1, N);

    // ---- layer 2 GEMM (f16 A exact, W2 f16-split, dis-scaled) + aggregate ----
    gemm16<OUTC, true, true><<<(N + 127) / 128, 256>>>(p_act1, W2, p_hs2, N, HID);
    k_agg64<<<(N * 32 + 255) / 256, 256>>>(p_hs2, out, b2, N);
}

// round 16
// speedup vs baseline: 1.1183x; 1.0035x over previous
#include <cuda_runtime.h>
#include <cuda_fp16.h>
#include <cuda_bf16.h>
#include <cstdint>

#define MAX_N 50000
#define MAX_E 800000
#define IN_C  256
#define HID   128
#define OUTC  64
#define SCAN_B 256
#define SCAN_NBLK ((MAX_N + SCAN_B - 1) / SCAN_B)   // 196

// ---- scratch (device globals: no allocations allowed) ----
__device__ int    g_is64;
__device__ int    g_csr[MAX_E];
__device__ int    g_cnt[MAX_N];
__device__ int    g_start[MAX_N];
__device__ int    g_cursor[MAX_N];
__device__ int    g_bsum[SCAN_NBLK];
__device__ float  g_dis[MAX_N];
__device__ __half g_hs1[MAX_N * HID];   // UNSCALED layer-1 GEMM output (f16)
__device__ __half g_act1[MAX_N * HID];  // relu'd layer-1 output (f16)
__device__ __half g_hs2[MAX_N * OUTC];  // dis-scaled layer-2 GEMM output (f16)

// ---------------- CSR build ----------------
__global__ void k_detect(const long long* __restrict__ ei) {
    __shared__ int ok;
    if (threadIdx.x == 0) ok = 1;
    __syncthreads();
    long long v = ei[threadIdx.x];
    if (v < 0 || v >= MAX_N) ok = 0;
    __syncthreads();
    if (threadIdx.x == 0) g_is64 = ok;
}

__global__ void k_hist(const void* __restrict__ ei, int E) {
    int i4 = (blockIdx.x * blockDim.x + threadIdx.x) * 4;
    if (i4 >= E) return;
    if (!g_is64 && i4 + 4 <= E) {
        int4 d = *reinterpret_cast<const int4*>((const int*)ei + E + i4);
        atomicAdd(&g_cnt[d.x], 1);
        atomicAdd(&g_cnt[d.y], 1);
        atomicAdd(&g_cnt[d.z], 1);
        atomicAdd(&g_cnt[d.w], 1);
    } else {
        for (int i = i4; i < min(i4 + 4, E); i++) {
            int d = g_is64 ? (int)((const long long*)ei)[i + E]
                           : ((const int*)ei)[i + E];
            atomicAdd(&g_cnt[d], 1);
        }
    }
}

__device__ __forceinline__ int warp_incl_scan(int v, int lane) {
#pragma unroll
    for (int off = 1; off < 32; off <<= 1) {
        int x = __shfl_up_sync(0xFFFFFFFFu, v, off);
        if (lane >= off) v += x;
    }
    return v;
}

// shuffle-based block scan: g_start[i] = exclusive prefix within block; g_bsum = block total
__global__ void k_scan1(int n) {
    __shared__ int wsum[8];
    int tid = threadIdx.x, lane = tid & 31, wid = tid >> 5;
    int i = blockIdx.x * SCAN_B + tid;
    int v = (i < n) ? g_cnt[i] : 0;
    int incl = warp_incl_scan(v, lane);
    if (lane == 31) wsum[wid] = incl;
    __syncthreads();
    if (wid == 0) {
        int t = (lane < 8) ? wsum[lane] : 0;
        int ts = warp_incl_scan(t, lane);
        if (lane < 8) wsum[lane] = ts - t;            // exclusive warp offsets
        if (lane == 7) g_bsum[blockIdx.x] = ts;       // block total
    }
    __syncthreads();
    if (i < n) g_start[i] = incl - v + wsum[wid];
}

// every block redundantly scans the 196 block sums (shuffle), then applies
__global__ void k_scan3(int n, int nblk) {
    __shared__ int s[SCAN_B];
    __shared__ int wsum[8];
    int tid = threadIdx.x, lane = tid & 31, wid = tid >> 5;
    int v = (tid < nblk) ? g_bsum[tid] : 0;
    int incl = warp_incl_scan(v, lane);
    if (lane == 31) wsum[wid] = incl;
    __syncthreads();
    if (wid == 0) {
        int t = (lane < 8) ? wsum[lane] : 0;
        int ts = warp_incl_scan(t, lane);
        if (lane < 8) wsum[lane] = ts - t;
    }
    __syncthreads();
    s[tid] = incl + wsum[wid];                        // full inclusive scan of bsum
    __syncthreads();
    int boff = (blockIdx.x == 0) ? 0 : s[blockIdx.x - 1];
    int i = blockIdx.x * SCAN_B + tid;
    if (i >= n) return;
    int st = g_start[i] + boff;
    g_start[i]  = st;
    g_cursor[i] = st;
    g_dis[i]    = rsqrtf((float)(g_cnt[i] + 1));
}

__global__ void k_fill(const void* __restrict__ ei, int E) {
    int i4 = (blockIdx.x * blockDim.x + threadIdx.x) * 4;
    if (i4 >= E) return;
    if (!g_is64 && i4 + 4 <= E) {
        int4 sv = *reinterpret_cast<const int4*>((const int*)ei + i4);
        int4 dv = *reinterpret_cast<const int4*>((const int*)ei + E + i4);
        g_csr[atomicAdd(&g_cursor[dv.x], 1)] = sv.x;
        g_csr[atomicAdd(&g_cursor[dv.y], 1)] = sv.y;
        g_csr[atomicAdd(&g_cursor[dv.z], 1)] = sv.z;
        g_csr[atomicAdd(&g_cursor[dv.w], 1)] = sv.w;
    } else {
        for (int i = i4; i < min(i4 + 4, E); i++) {
            int sIdx, d;
            if (g_is64) {
                const long long* p = (const long long*)ei;
                sIdx = (int)p[i]; d = (int)p[i + E];
            } else {
                const int* p = (const int*)ei;
                sIdx = p[i]; d = p[i + E];
            }
            g_csr[atomicAdd(&g_cursor[d], 1)] = sIdx;
        }
    }
}

// ---------------- 16-bit k16 tensor-core GEMM (FROZEN from R11) ----------------
__device__ __forceinline__ void mma16b(float* c, const unsigned* a, const unsigned* b) {
    asm volatile(
        "mma.sync.aligned.m16n8k16.row.col.f32.bf16.bf16.f32 "
        "{%0,%1,%2,%3},{%4,%5,%6,%7},{%8,%9},{%0,%1,%2,%3};"
        : "+f"(c[0]), "+f"(c[1]), "+f"(c[2]), "+f"(c[3])
        : "r"(a[0]), "r"(a[1]), "r"(a[2]), "r"(a[3]), "r"(b[0]), "r"(b[1]));
}

__device__ __forceinline__ void mma16h(float* c, const unsigned* a, const unsigned* b) {
    asm volatile(
        "mma.sync.aligned.m16n8k16.row.col.f32.f16.f16.f32 "
        "{%0,%1,%2,%3},{%4,%5,%6,%7},{%8,%9},{%0,%1,%2,%3};"
        : "+f"(c[0]), "+f"(c[1]), "+f"(c[2]), "+f"(c[3])
        : "r"(a[0]), "r"(a[1]), "r"(a[2]), "r"(a[3]), "r"(b[0]), "r"(b[1]));
}

__device__ __forceinline__ void split2_bf16(float e, float o, unsigned& hi, unsigned& lo) {
    __nv_bfloat16 he = __float2bfloat16_rn(e), ho = __float2bfloat16_rn(o);
    float re = e - __bfloat162float(he), ro = o - __bfloat162float(ho);
    __nv_bfloat162 h; h.x = he; h.y = ho;
    __nv_bfloat162 l = __floats2bfloat162_rn(re, ro);
    hi = *reinterpret_cast<unsigned*>(&h);
    lo = *reinterpret_cast<unsigned*>(&l);
}

__device__ __forceinline__ void split2_f16(float e, float o, unsigned& hi, unsigned& lo) {
    __half he = __float2half_rn(e), ho = __float2half_rn(o);
    float re = e - __half2float(he), ro = o - __half2float(ho);
    __half2 h; h.x = he; h.y = ho;
    __half2 l = __floats2half2_rn(re, ro);
    hi = *reinterpret_cast<unsigned*>(&h);
    lo = *reinterpret_cast<unsigned*>(&l);
}

template<int BN, bool SCALE, bool FP16A>
__global__ void __launch_bounds__(256)
gemm16(const void* __restrict__ Av, const float* __restrict__ W,
       __half* __restrict__ out, int M, int K)
{
    constexpr int BM = 128, BK = 16;
    constexpr int LDP = 12;
    constexpr int NF  = BN / 16;
    constexpr int B_PITER = BN / 32;

    __shared__ unsigned As_hi[BM * LDP];
    __shared__ unsigned As_lo[FP16A ? 1 : BM * LDP];
    __shared__ unsigned Bs_hi[BN * LDP], Bs_lo[BN * LDP];

    const int tid  = threadIdx.x;
    const int lane = tid & 31, warp = tid >> 5;
    const int wm = warp & 3, wn = warp >> 2;
    const int row0 = blockIdx.x * BM;

    float acc[2][NF][4] = {};

    uint4  ra_h;
    float4 ra_f0, ra_f1;
    float  rbe[B_PITER], rbo[B_PITER];

    auto loadTiles = [&](int kk) {
        if (FP16A) {
            const __half* A = (const __half*)Av;
            int r = tid >> 1, c = (tid & 1) * 8;
            ra_h = make_uint4(0, 0, 0, 0);
            if (row0 + r < M)
                ra_h = *reinterpret_cast<const uint4*>(A + (size_t)(row0 + r) * K + kk + c);
        } else {
            const float* A = (const float*)Av;
            int r = tid >> 2, c = (tid & 3) * 4;
            ra_f0 = make_float4(0.f, 0.f, 0.f, 0.f);
            ra_f1 = make_float4(0.f, 0.f, 0.f, 0.f);
            if (row0 + r < M)
                ra_f0 = *reinterpret_cast<const float4*>(A + (size_t)(row0 + r) * K + kk + c);
            if (row0 + r + 64 < M)
                ra_f1 = *reinterpret_cast<const float4*>(A + (size_t)(row0 + r + 64) * K + kk + c);
        }
#pragma unroll
        for (int i = 0; i < B_PITER; i++) {
            int idx = tid + i * 256;
            int kp = idx / BN, n = idx % BN;
            rbe[i] = W[(size_t)(kk + 2 * kp    ) * BN + n];
            rbo[i] = W[(size_t)(kk + 2 * kp + 1) * BN + n];
        }
    };

    auto storeTiles = [&]() {
        if (FP16A) {
            int r = tid >> 1, p0 = (tid & 1) * 4;
            As_hi[r*LDP + p0    ] = ra_h.x;
            As_hi[r*LDP + p0 + 1] = ra_h.y;
            As_hi[r*LDP + p0 + 2] = ra_h.z;
            As_hi[r*LDP + p0 + 3] = ra_h.w;
        } else {
            int r = tid >> 2, p0 = (tid & 3) * 2;
            unsigned h, l;
            split2_bf16(ra_f0.x, ra_f0.y, h, l); As_hi[r*LDP + p0    ] = h; As_lo[r*LDP + p0    ] = l;
            split2_bf16(ra_f0.z, ra_f0.w, h, l); As_hi[r*LDP + p0 + 1] = h; As_lo[r*LDP + p0 + 1] = l;
            int r1 = r + 64;
            split2_bf16(ra_f1.x, ra_f1.y, h, l); As_hi[r1*LDP + p0    ] = h; As_lo[r1*LDP + p0    ] = l;
            split2_bf16(ra_f1.z, ra_f1.w, h, l); As_hi[r1*LDP + p0 + 1] = h; As_lo[r1*LDP + p0 + 1] = l;
        }
#pragma unroll
        for (int i = 0; i < B_PITER; i++) {
            int idx = tid + i * 256;
            int kp = idx / BN, n = idx % BN;
            unsigned h, l;
            if (FP16A) split2_f16 (rbe[i], rbo[i], h, l);
            else       split2_bf16(rbe[i], rbo[i], h, l);
            Bs_hi[n*LDP + kp] = h;
            Bs_lo[n*LDP + kp] = l;
        }
    };

    auto compute = [&]() {
        unsigned ah[2][4], al[2][4];
        const int q = lane & 3;
#pragma unroll
        for (int mf = 0; mf < 2; mf++) {
            int r = wm * 32 + mf * 16 + (lane >> 2);
            ah[mf][0] = As_hi[ r      * LDP + q    ];
            ah[mf][1] = As_hi[(r + 8) * LDP + q    ];
            ah[mf][2] = As_hi[ r      * LDP + q + 4];
            ah[mf][3] = As_hi[(r + 8) * LDP + q + 4];
            if (!FP16A) {
                al[mf][0] = As_lo[ r      * LDP + q    ];
                al[mf][1] = As_lo[(r + 8) * LDP + q    ];
                al[mf][2] = As_lo[ r      * LDP + q + 4];
                al[mf][3] = As_lo[(r + 8) * LDP + q + 4];
            }
        }
#pragma unroll
        for (int nf = 0; nf < NF; nf++) {
            int n = wn * (BN / 2) + nf * 8 + (lane >> 2);
            unsigned bh[2], bl[2];
            bh[0] = Bs_hi[n*LDP + q];
            bh[1] = Bs_hi[n*LDP + q + 4];
            bl[0] = Bs_lo[n*LDP + q];
            bl[1] = Bs_lo[n*LDP + q + 4];
#pragma unroll
            for (int mf = 0; mf < 2; mf++) {
                if (FP16A) {
                    mma16h(acc[mf][nf], ah[mf], bh);
                    mma16h(acc[mf][nf], ah[mf], bl);
                } else {
                    mma16b(acc[mf][nf], ah[mf], bh);
                    mma16b(acc[mf][nf], ah[mf], bl);
                    mma16b(acc[mf][nf], al[mf], bh);
                }
            }
        }
    };

    loadTiles(0);
    storeTiles();
    __syncthreads();
    for (int kk = BK; kk < K; kk += BK) {
        loadTiles(kk);
        compute();
        __syncthreads();
        storeTiles();
        __syncthreads();
    }
    compute();

#pragma unroll
    for (int mf = 0; mf < 2; mf++) {
        int r0 = row0 + wm * 32 + mf * 16 + (lane >> 2);
        int r1 = r0 + 8;
        float d0 = 1.f, d1 = 1.f;
        if (SCALE) {
            d0 = (r0 < M) ? g_dis[r0] : 0.f;
            d1 = (r1 < M) ? g_dis[r1] : 0.f;
        }
#pragma unroll
        for (int nf = 0; nf < NF; nf++) {
            int c = wn * (BN / 2) + nf * 8 + (lane & 3) * 2;
            if (r0 < M)
                *reinterpret_cast<__half2*>(out + (size_t)r0 * BN + c) =
                    __floats2half2_rn(acc[mf][nf][0] * d0, acc[mf][nf][1] * d0);
            if (r1 < M)
                *reinterpret_cast<__half2*>(out + (size_t)r1 * BN + c) =
                    __floats2half2_rn(acc[mf][nf][2] * d1, acc[mf][nf][3] * d1);
        }
    }
}

// ---------------- gather aggregation (R11 proven shapes — FROZEN) ----------------
__device__ __forceinline__ void acch(float* a, uint2 v, float s) {
    __half2 h0 = *reinterpret_cast<__half2*>(&v.x);
    __half2 h1 = *reinterpret_cast<__half2*>(&v.y);
    float2 f0 = __half22float2(h0), f1 = __half22float2(h1);
    a[0] = fmaf(s, f0.x, a[0]);
    a[1] = fmaf(s, f0.y, a[1]);
    a[2] = fmaf(s, f1.x, a[2]);
    a[3] = fmaf(s, f1.y, a[3]);
}

__device__ __forceinline__ void acch2(float* a, unsigned v, float s) {
    float2 f = __half22float2(*reinterpret_cast<__half2*>(&v));
    a[0] = fmaf(s, f.x, a[0]);
    a[1] = fmaf(s, f.y, a[1]);
}

// layer 1: one warp per node, 8B per lane
__global__ void k_agg128(const __half* __restrict__ hs, __half* __restrict__ out,
                         const float* __restrict__ bias, int N)
{
    int w = (blockIdx.x * blockDim.x + threadIdx.x) >> 5;
    if (w >= N) return;
    int lane = threadIdx.x & 31;
    const uint2* base = (const uint2*)hs;

    int beg = g_start[w], cnt = g_cnt[w];
    float dw = g_dis[w];
    float a[4] = {0.f, 0.f, 0.f, 0.f};
    acch(a, base[(size_t)w * 32 + lane], dw);   // self loop

    int e = 0;
    for (; e + 8 <= cnt; e += 8) {
        int s0 = g_csr[beg+e  ], s1 = g_csr[beg+e+1], s2 = g_csr[beg+e+2], s3 = g_csr[beg+e+3];
        int s4 = g_csr[beg+e+4], s5 = g_csr[beg+e+5], s6 = g_csr[beg+e+6], s7 = g_csr[beg+e+7];
        uint2 v0 = base[(size_t)s0*32+lane], v1 = base[(size_t)s1*32+lane];
        uint2 v2 = base[(size_t)s2*32+lane], v3 = base[(size_t)s3*32+lane];
        uint2 v4 = base[(size_t)s4*32+lane], v5 = base[(size_t)s5*32+lane];
        uint2 v6 = base[(size_t)s6*32+lane], v7 = base[(size_t)s7*32+lane];
        acch(a, v0, g_dis[s0]); acch(a, v1, g_dis[s1]);
        acch(a, v2, g_dis[s2]); acch(a, v3, g_dis[s3]);
        acch(a, v4, g_dis[s4]); acch(a, v5, g_dis[s5]);
        acch(a, v6, g_dis[s6]); acch(a, v7, g_dis[s7]);
    }
    for (; e < cnt; e++) {
        int s = g_csr[beg + e];
        acch(a, base[(size_t)s*32+lane], g_dis[s]);
    }

    float4 b = ((const float4*)bias)[lane];
    uint2 r;
    __half2 r0 = __floats2half2_rn(fmaxf(fmaf(dw, a[0], b.x), 0.f),
                                   fmaxf(fmaf(dw, a[1], b.y), 0.f));
    __half2 r1 = __floats2half2_rn(fmaxf(fmaf(dw, a[2], b.z), 0.f),
                                   fmaxf(fmaf(dw, a[3], b.w), 0.f));
    r.x = *reinterpret_cast<unsigned*>(&r0);
    r.y = *reinterpret_cast<unsigned*>(&r1);
    ((uint2*)out)[(size_t)w * 32 + lane] = r;
}

// layer 2: one warp per node, 4B (half2) per lane
__global__ void k_agg64(const __half* __restrict__ hs, float* __restrict__ out,
                        const float* __restrict__ bias, int N)
{
    int node = (blockIdx.x * blockDim.x + threadIdx.x) >> 5;
    if (node >= N) return;
    int lane = threadIdx.x & 31;
    const unsigned* base = (const unsigned*)hs;

    int beg = g_start[node], cnt = g_cnt[node];
    float a[2] = {0.f, 0.f};
    acch2(a, base[(size_t)node * 32 + lane], 1.f);   // self loop (already scaled)

    int e = 0;
    for (; e + 8 <= cnt; e += 8) {
        int s0 = g_csr[beg+e  ], s1 = g_csr[beg+e+1], s2 = g_csr[beg+e+2], s3 = g_csr[beg+e+3];
        int s4 = g_csr[beg+e+4], s5 = g_csr[beg+e+5], s6 = g_csr[beg+e+6], s7 = g_csr[beg+e+7];
        unsigned v0 = base[(size_t)s0*32+lane], v1 = base[(size_t)s1*32+lane];
        unsigned v2 = base[(size_t)s2*32+lane], v3 = base[(size_t)s3*32+lane];
        unsigned v4 = base[(size_t)s4*32+lane], v5 = base[(size_t)s5*32+lane];
        unsigned v6 = base[(size_t)s6*32+lane], v7 = base[(size_t)s7*32+lane];
        acch2(a, v0, 1.f); acch2(a, v1, 1.f); acch2(a, v2, 1.f); acch2(a, v3, 1.f);
        acch2(a, v4, 1.f); acch2(a, v5, 1.f); acch2(a, v6, 1.f); acch2(a, v7, 1.f);
    }
    for (; e < cnt; e++)
        acch2(a, base[(size_t)g_csr[beg+e]*32+lane], 1.f);

    float dw = g_dis[node];
    float2 b = ((const float2*)bias)[lane];
    float2 r;
    r.x = fmaf(dw, a[0], b.x);
    r.y = fmaf(dw, a[1], b.y);
    ((float2*)out)[(size_t)node * 32 + lane] = r;
}

// ---------------- launch ----------------
extern "C" void kernel_launch(void* const* d_in, const int* in_sizes, int n_in,
                              void* d_out, int out_size)
{
    const float* x   = (const float*)d_in[0];
    const void*  ei  = d_in[1];
    const float* W1  = (const float*)d_in[2];
    const float* b1  = (const float*)d_in[3];
    const float* W2  = (const float*)d_in[4];
    const float* b2  = (const float*)d_in[5];
    float*       out = (float*)d_out;

    const int N = in_sizes[0] / IN_C;   // 50000
    const int E = in_sizes[1] / 2;      // 800000
    const int nscan = (N + SCAN_B - 1) / SCAN_B;
    const int e4blocks = ((E + 3) / 4 + 255) / 256;

    __half *p_hs1, *p_act1, *p_hs2;
    int    *p_cnt;
    cudaGetSymbolAddress((void**)&p_hs1,  g_hs1);
    cudaGetSymbolAddress((void**)&p_act1, g_act1);
    cudaGetSymbolAddress((void**)&p_hs2,  g_hs2);
    cudaGetSymbolAddress((void**)&p_cnt,  g_cnt);

    static cudaStream_t s2 = nullptr;
    static cudaEvent_t evFork = nullptr, evJoin = nullptr;
    if (!s2) {
        if (cudaStreamCreateWithFlags(&s2, cudaStreamNonBlocking) != cudaSuccess) s2 = nullptr;
        if (s2) {
            cudaEventCreateWithFlags(&evFork, cudaEventDisableTiming);
            cudaEventCreateWithFlags(&evJoin, cudaEventDisableTiming);
        }
    }

    // ---- fork: GEMM1 (split-bf16) on side stream, overlapping CSR build ----
    bool forked = false;
    if (s2) {
        cudaEventRecord(evFork, 0);
        cudaStreamWaitEvent(s2, evFork, 0);
        gemm16<HID, false, false><<<(N + 127) / 128, 256, 0, s2>>>(x, W1, p_hs1, N, IN_C);
        cudaEventRecord(evJoin, s2);
        forked = true;
    }

    // ---- main stream: CSR build + dis ----
    cudaMemsetAsync(p_cnt, 0, (size_t)N * sizeof(int), 0);   // DMA-path zeroing
    k_detect<<<1, 256>>>((const long long*)ei);
    k_hist<<<e4blocks, 256>>>(ei, E);
    k_scan1<<<nscan, SCAN_B>>>(N);
    k_scan3<<<nscan, SCAN_B>>>(N, nscan);
    k_fill<<<e4blocks, 256>>>(ei, E);

    if (forked) cudaStreamWaitEvent(0, evJoin, 0);
    else        gemm16<HID, false, false><<<(N + 127) / 128, 256>>>(x, W1, p_hs1, N, IN_C);

    // ---- layer 1 aggregate (+dis both sides, bias, relu) -> f16 act1 ----
    k_agg128<<<(N * 32 + 255) / 256, 256>>>(p_hs1, p_act1, b1, N);

    // ---- layer 2 GEMM (f16 A exact, W2 f16-split, dis-scaled) + aggregate ----
    gemm16<OUTC, true, true><<<(N + 127) / 128, 256>>>(p_act1, W2, p_hs2, N, HID);
    k_agg64<<<(N * 32 + 255) / 256, 256>>>(p_hs2, out, b2, N);
}

// round 17
// speedup vs baseline: 1.1282x; 1.0088x over previous
#include <cuda_runtime.h>
#include <cuda_fp16.h>
#include <cuda_bf16.h>
#include <cstdint>

#define MAX_N 50000
#define MAX_E 800000
#define IN_C  256
#define HID   128
#define OUTC  64
#define SCAN_B 256
#define SCAN_NBLK ((MAX_N + SCAN_B - 1) / SCAN_B)   // 196

// ---- scratch (device globals: no allocations allowed) ----
__device__ int    g_csr[MAX_E];
__device__ int    g_cnt[MAX_N];
__device__ int    g_start[MAX_N];
__device__ int    g_cursor[MAX_N];
__device__ unsigned long long g_desc[SCAN_NBLK];   // decoupled-lookback: (value<<2)|flag
__device__ float  g_dis[MAX_N];
__device__ __half g_hs1[MAX_N * HID];   // UNSCALED layer-1 GEMM output (f16)
__device__ __half g_act1[MAX_N * HID];  // relu'd layer-1 output (f16)
__device__ __half g_hs2[MAX_N * OUTC];  // dis-scaled layer-2 GEMM output (f16)

// ---------------- inline edge-index dtype detection ----------------
// int32 read as int64 combines two random indices -> >= 2^32 unless high word
// is exactly 0 (p = 1/50000 each). 4 checks -> misdetect p ~ 1.6e-19.
__device__ __forceinline__ bool detect_is64(const void* ei) {
    const long long* p = (const long long*)ei;
#pragma unroll
    for (int i = 0; i < 4; i++) {
        long long v = p[i];
        if (v < 0 || v >= MAX_N) return false;
    }
    return true;
}

// ---------------- CSR build ----------------
__global__ void k_hist(const void* __restrict__ ei, int E) {
    int i4 = (blockIdx.x * blockDim.x + threadIdx.x) * 4;
    if (i4 >= E) return;
    bool is64 = detect_is64(ei);
    if (!is64 && i4 + 4 <= E) {
        int4 d = *reinterpret_cast<const int4*>((const int*)ei + E + i4);
        atomicAdd(&g_cnt[d.x], 1);
        atomicAdd(&g_cnt[d.y], 1);
        atomicAdd(&g_cnt[d.z], 1);
        atomicAdd(&g_cnt[d.w], 1);
    } else {
        for (int i = i4; i < min(i4 + 4, E); i++) {
            int d = is64 ? (int)((const long long*)ei)[i + E]
                         : ((const int*)ei)[i + E];
            atomicAdd(&g_cnt[d], 1);
        }
    }
}

__device__ __forceinline__ int warp_incl_scan(int v, int lane) {
#pragma unroll
    for (int off = 1; off < 32; off <<= 1) {
        int x = __shfl_up_sync(0xFFFFFFFFu, v, off);
        if (lane >= off) v += x;
    }
    return v;
}

// single-pass scan with decoupled lookback: computes g_start/g_cursor/g_dis in ONE kernel
__global__ void k_scan(int n) {
    __shared__ int wtot[8];
    __shared__ int s_ex;
    const int tid = threadIdx.x, lane = tid & 31, wid = tid >> 5, bid = blockIdx.x;
    const int i = bid * SCAN_B + tid;

    int c = (i < n) ? g_cnt[i] : 0;
    int incl = warp_incl_scan(c, lane);
    if (lane == 31) wtot[wid] = incl;
    __syncthreads();

    int woff = 0;
#pragma unroll
    for (int k = 0; k < 8; k++) woff += (k < wid) ? wtot[k] : 0;
    int blockTotal = 0;
#pragma unroll
    for (int k = 0; k < 8; k++) blockTotal += wtot[k];

    // warp 0: publish + lookback
    if (wid == 0) {
        if (bid == 0) {
            if (lane == 0) {
                atomicExch(&g_desc[0], ((unsigned long long)blockTotal << 2) | 2ULL);
                s_ex = 0;
            }
        } else {
            if (lane == 0)
                atomicExch(&g_desc[bid], ((unsigned long long)blockTotal << 2) | 1ULL);
            int ex = 0;
            int p = bid - 1;
            while (true) {
                int idx = p - lane;
                unsigned long long d;
                int f;
                do {
                    d = (idx >= 0) ? atomicAdd(&g_desc[idx], 0ULL)
                                   : 2ULL;                      // virtual "-1" block: inclusive 0
                    f = (int)(d & 3ULL);
                } while (f == 0);
                int v = (int)(d >> 2);
                unsigned mIncl = __ballot_sync(0xFFFFFFFFu, idx >= 0 && f == 2);
                if (mIncl) {
                    int l = __ffs(mIncl) - 1;   // nearest (lowest-lane) inclusive predecessor
                    int contrib = (lane <= l && idx >= 0) ? v : 0;
#pragma unroll
                    for (int off = 16; off > 0; off >>= 1)
                        contrib += __shfl_down_sync(0xFFFFFFFFu, contrib, off);
                    ex += __shfl_sync(0xFFFFFFFFu, contrib, 0);
                    break;
                } else {
                    int contrib = (idx >= 0) ? v : 0;
#pragma unroll
                    for (int off = 16; off > 0; off >>= 1)
                        contrib += __shfl_down_sync(0xFFFFFFFFu, contrib, off);
                    ex += __shfl_sync(0xFFFFFFFFu, contrib, 0);
                    p -= 32;
                    if (p < 0 && (p + 32) <= 0) break;  // all predecessors consumed
                }
            }
            if (lane == 0) {
                atomicExch(&g_desc[bid],
                           ((unsigned long long)(ex + blockTotal) << 2) | 2ULL);
                s_ex = ex;
            }
        }
    }
    __syncthreads();

    if (i >= n) return;
    int st = s_ex + woff + (incl - c);   // global exclusive prefix
    g_start[i]  = st;
    g_cursor[i] = st;
    g_dis[i]    = rsqrtf((float)(c + 1));
}

__global__ void k_fill(const void* __restrict__ ei, int E) {
    int i4 = (blockIdx.x * blockDim.x + threadIdx.x) * 4;
    if (i4 >= E) return;
    bool is64 = detect_is64(ei);
    if (!is64 && i4 + 4 <= E) {
        int4 sv = *reinterpret_cast<const int4*>((const int*)ei + i4);
        int4 dv = *reinterpret_cast<const int4*>((const int*)ei + E + i4);
        g_csr[atomicAdd(&g_cursor[dv.x], 1)] = sv.x;
        g_csr[atomicAdd(&g_cursor[dv.y], 1)] = sv.y;
        g_csr[atomicAdd(&g_cursor[dv.z], 1)] = sv.z;
        g_csr[atomicAdd(&g_cursor[dv.w], 1)] = sv.w;
    } else {
        for (int i = i4; i < min(i4 + 4, E); i++) {
            int sIdx, d;
            if (is64) {
                const long long* p = (const long long*)ei;
                sIdx = (int)p[i]; d = (int)p[i + E];
            } else {
                const int* p = (const int*)ei;
                sIdx = p[i]; d = p[i + E];
            }
            g_csr[atomicAdd(&g_cursor[d], 1)] = sIdx;
        }
    }
}

// ---------------- 16-bit k16 tensor-core GEMM (FROZEN) ----------------
__device__ __forceinline__ void mma16b(float* c, const unsigned* a, const unsigned* b) {
    asm volatile(
        "mma.sync.aligned.m16n8k16.row.col.f32.bf16.bf16.f32 "
        "{%0,%1,%2,%3},{%4,%5,%6,%7},{%8,%9},{%0,%1,%2,%3};"
        : "+f"(c[0]), "+f"(c[1]), "+f"(c[2]), "+f"(c[3])
        : "r"(a[0]), "r"(a[1]), "r"(a[2]), "r"(a[3]), "r"(b[0]), "r"(b[1]));
}

__device__ __forceinline__ void mma16h(float* c, const unsigned* a, const unsigned* b) {
    asm volatile(
        "mma.sync.aligned.m16n8k16.row.col.f32.f16.f16.f32 "
        "{%0,%1,%2,%3},{%4,%5,%6,%7},{%8,%9},{%0,%1,%2,%3};"
        : "+f"(c[0]), "+f"(c[1]), "+f"(c[2]), "+f"(c[3])
        : "r"(a[0]), "r"(a[1]), "r"(a[2]), "r"(a[3]), "r"(b[0]), "r"(b[1]));
}

__device__ __forceinline__ void split2_bf16(float e, float o, unsigned& hi, unsigned& lo) {
    __nv_bfloat16 he = __float2bfloat16_rn(e), ho = __float2bfloat16_rn(o);
    float re = e - __bfloat162float(he), ro = o - __bfloat162float(ho);
    __nv_bfloat162 h; h.x = he; h.y = ho;
    __nv_bfloat162 l = __floats2bfloat162_rn(re, ro);
    hi = *reinterpret_cast<unsigned*>(&h);
    lo = *reinterpret_cast<unsigned*>(&l);
}

__device__ __forceinline__ void split2_f16(float e, float o, unsigned& hi, unsigned& lo) {
    __half he = __float2half_rn(e), ho = __float2half_rn(o);
    float re = e - __half2float(he), ro = o - __half2float(ho);
    __half2 h; h.x = he; h.y = ho;
    __half2 l = __floats2half2_rn(re, ro);
    hi = *reinterpret_cast<unsigned*>(&h);
    lo = *reinterpret_cast<unsigned*>(&l);
}

template<int BN, bool SCALE, bool FP16A>
__global__ void __launch_bounds__(256)
gemm16(const void* __restrict__ Av, const float* __restrict__ W,
       __half* __restrict__ out, int M, int K)
{
    constexpr int BM = 128, BK = 16;
    constexpr int LDP = 12;
    constexpr int NF  = BN / 16;
    constexpr int B_PITER = BN / 32;

    __shared__ unsigned As_hi[BM * LDP];
    __shared__ unsigned As_lo[FP16A ? 1 : BM * LDP];
    __shared__ unsigned Bs_hi[BN * LDP], Bs_lo[BN * LDP];

    const int tid  = threadIdx.x;
    const int lane = tid & 31, warp = tid >> 5;
    const int wm = warp & 3, wn = warp >> 2;
    const int row0 = blockIdx.x * BM;

    float acc[2][NF][4] = {};

    uint4  ra_h;
    float4 ra_f0, ra_f1;
    float  rbe[B_PITER], rbo[B_PITER];

    auto loadTiles = [&](int kk) {
        if (FP16A) {
            const __half* A = (const __half*)Av;
            int r = tid >> 1, c = (tid & 1) * 8;
            ra_h = make_uint4(0, 0, 0, 0);
            if (row0 + r < M)
                ra_h = *reinterpret_cast<const uint4*>(A + (size_t)(row0 + r) * K + kk + c);
        } else {
            const float* A = (const float*)Av;
            int r = tid >> 2, c = (tid & 3) * 4;
            ra_f0 = make_float4(0.f, 0.f, 0.f, 0.f);
            ra_f1 = make_float4(0.f, 0.f, 0.f, 0.f);
            if (row0 + r < M)
                ra_f0 = *reinterpret_cast<const float4*>(A + (size_t)(row0 + r) * K + kk + c);
            if (row0 + r + 64 < M)
                ra_f1 = *reinterpret_cast<const float4*>(A + (size_t)(row0 + r + 64) * K + kk + c);
        }
#pragma unroll
        for (int i = 0; i < B_PITER; i++) {
            int idx = tid + i * 256;
            int kp = idx / BN, n = idx % BN;
            rbe[i] = W[(size_t)(kk + 2 * kp    ) * BN + n];
            rbo[i] = W[(size_t)(kk + 2 * kp + 1) * BN + n];
        }
    };

    auto storeTiles = [&]() {
        if (FP16A) {
            int r = tid >> 1, p0 = (tid & 1) * 4;
            As_hi[r*LDP + p0    ] = ra_h.x;
            As_hi[r*LDP + p0 + 1] = ra_h.y;
            As_hi[r*LDP + p0 + 2] = ra_h.z;
            As_hi[r*LDP + p0 + 3] = ra_h.w;
        } else {
            int r = tid >> 2, p0 = (tid & 3) * 2;
            unsigned h, l;
            split2_bf16(ra_f0.x, ra_f0.y, h, l); As_hi[r*LDP + p0    ] = h; As_lo[r*LDP + p0    ] = l;
            split2_bf16(ra_f0.z, ra_f0.w, h, l); As_hi[r*LDP + p0 + 1] = h; As_lo[r*LDP + p0 + 1] = l;
            int r1 = r + 64;
            split2_bf16(ra_f1.x, ra_f1.y, h, l); As_hi[r1*LDP + p0    ] = h; As_lo[r1*LDP + p0    ] = l;
            split2_bf16(ra_f1.z, ra_f1.w, h, l); As_hi[r1*LDP + p0 + 1] = h; As_lo[r1*LDP + p0 + 1] = l;
        }
#pragma unroll
        for (int i = 0; i < B_PITER; i++) {
            int idx = tid + i * 256;
            int kp = idx / BN, n = idx % BN;
            unsigned h, l;
            if (FP16A) split2_f16 (rbe[i], rbo[i], h, l);
            else       split2_bf16(rbe[i], rbo[i], h, l);
            Bs_hi[n*LDP + kp] = h;
            Bs_lo[n*LDP + kp] = l;
        }
    };

    auto compute = [&]() {
        unsigned ah[2][4], al[2][4];
        const int q = lane & 3;
#pragma unroll
        for (int mf = 0; mf < 2; mf++) {
            int r = wm * 32 + mf * 16 + (lane >> 2);
            ah[mf][0] = As_hi[ r      * LDP + q    ];
            ah[mf][1] = As_hi[(r + 8) * LDP + q    ];
            ah[mf][2] = As_hi[ r      * LDP + q + 4];
            ah[mf][3] = As_hi[(r + 8) * LDP + q + 4];
            if (!FP16A) {
                al[mf][0] = As_lo[ r      * LDP + q    ];
                al[mf][1] = As_lo[(r + 8) * LDP + q    ];
                al[mf][2] = As_lo[ r      * LDP + q + 4];
                al[mf][3] = As_lo[(r + 8) * LDP + q + 4];
            }
        }
#pragma unroll
        for (int nf = 0; nf < NF; nf++) {
            int n = wn * (BN / 2) + nf * 8 + (lane >> 2);
            unsigned bh[2], bl[2];
            bh[0] = Bs_hi[n*LDP + q];
            bh[1] = Bs_hi[n*LDP + q + 4];
            bl[0] = Bs_lo[n*LDP + q];
            bl[1] = Bs_lo[n*LDP + q + 4];
#pragma unroll
            for (int mf = 0; mf < 2; mf++) {
                if (FP16A) {
                    mma16h(acc[mf][nf], ah[mf], bh);
                    mma16h(acc[mf][nf], ah[mf], bl);
                } else {
                    mma16b(acc[mf][nf], ah[mf], bh);
                    mma16b(acc[mf][nf], ah[mf], bl);
                    mma16b(acc[mf][nf], al[mf], bh);
                }
            }
        }
    };

    loadTiles(0);
    storeTiles();
    __syncthreads();
    for (int kk = BK; kk < K; kk += BK) {
        loadTiles(kk);
        compute();
        __syncthreads();
        storeTiles();
        __syncthreads();
    }
    compute();

#pragma unroll
    for (int mf = 0; mf < 2; mf++) {
        int r0 = row0 + wm * 32 + mf * 16 + (lane >> 2);
        int r1 = r0 + 8;
        float d0 = 1.f, d1 = 1.f;
        if (SCALE) {
            d0 = (r0 < M) ? g_dis[r0] : 0.f;
            d1 = (r1 < M) ? g_dis[r1] : 0.f;
        }
#pragma unroll
        for (int nf = 0; nf < NF; nf++) {
            int c = wn * (BN / 2) + nf * 8 + (lane & 3) * 2;
            if (r0 < M)
                *reinterpret_cast<__half2*>(out + (size_t)r0 * BN + c) =
                    __floats2half2_rn(acc[mf][nf][0] * d0, acc[mf][nf][1] * d0);
            if (r1 < M)
                *reinterpret_cast<__half2*>(out + (size_t)r1 * BN + c) =
                    __floats2half2_rn(acc[mf][nf][2] * d1, acc[mf][nf][3] * d1);
        }
    }
}

// ---------------- gather aggregation (FROZEN R11 shapes) ----------------
__device__ __forceinline__ void acch(float* a, uint2 v, float s) {
    __half2 h0 = *reinterpret_cast<__half2*>(&v.x);
    __half2 h1 = *reinterpret_cast<__half2*>(&v.y);
    float2 f0 = __half22float2(h0), f1 = __half22float2(h1);
    a[0] = fmaf(s, f0.x, a[0]);
    a[1] = fmaf(s, f0.y, a[1]);
    a[2] = fmaf(s, f1.x, a[2]);
    a[3] = fmaf(s, f1.y, a[3]);
}

__device__ __forceinline__ void acch2(float* a, unsigned v, float s) {
    float2 f = __half22float2(*reinterpret_cast<__half2*>(&v));
    a[0] = fmaf(s, f.x, a[0]);
    a[1] = fmaf(s, f.y, a[1]);
}

// layer 1: one warp per node, 8B per lane
__global__ void k_agg128(const __half* __restrict__ hs, __half* __restrict__ out,
                         const float* __restrict__ bias, int N)
{
    int w = (blockIdx.x * blockDim.x + threadIdx.x) >> 5;
    if (w >= N) return;
    int lane = threadIdx.x & 31;
    const uint2* base = (const uint2*)hs;

    int beg = g_start[w], cnt = g_cnt[w];
    float dw = g_dis[w];
    float a[4] = {0.f, 0.f, 0.f, 0.f};
    acch(a, base[(size_t)w * 32 + lane], dw);   // self loop

    int e = 0;
    for (; e + 8 <= cnt; e += 8) {
        int s0 = g_csr[beg+e  ], s1 = g_csr[beg+e+1], s2 = g_csr[beg+e+2], s3 = g_csr[beg+e+3];
        int s4 = g_csr[beg+e+4], s5 = g_csr[beg+e+5], s6 = g_csr[beg+e+6], s7 = g_csr[beg+e+7];
        uint2 v0 = base[(size_t)s0*32+lane], v1 = base[(size_t)s1*32+lane];
        uint2 v2 = base[(size_t)s2*32+lane], v3 = base[(size_t)s3*32+lane];
        uint2 v4 = base[(size_t)s4*32+lane], v5 = base[(size_t)s5*32+lane];
        uint2 v6 = base[(size_t)s6*32+lane], v7 = base[(size_t)s7*32+lane];
        acch(a, v0, g_dis[s0]); acch(a, v1, g_dis[s1]);
        acch(a, v2, g_dis[s2]); acch(a, v3, g_dis[s3]);
        acch(a, v4, g_dis[s4]); acch(a, v5, g_dis[s5]);
        acch(a, v6, g_dis[s6]); acch(a, v7, g_dis[s7]);
    }
    for (; e < cnt; e++) {
        int s = g_csr[beg + e];
        acch(a, base[(size_t)s*32+lane], g_dis[s]);
    }

    float4 b = ((const float4*)bias)[lane];
    uint2 r;
    __half2 r0 = __floats2half2_rn(fmaxf(fmaf(dw, a[0], b.x), 0.f),
                                   fmaxf(fmaf(dw, a[1], b.y), 0.f));
    __half2 r1 = __floats2half2_rn(fmaxf(fmaf(dw, a[2], b.z), 0.f),
                                   fmaxf(fmaf(dw, a[3], b.w), 0.f));
    r.x = *reinterpret_cast<unsigned*>(&r0);
    r.y = *reinterpret_cast<unsigned*>(&r1);
    ((uint2*)out)[(size_t)w * 32 + lane] = r;
}

// layer 2: one warp per node, 4B (half2) per lane
__global__ void k_agg64(const __half* __restrict__ hs, float* __restrict__ out,
                        const float* __restrict__ bias, int N)
{
    int node = (blockIdx.x * blockDim.x + threadIdx.x) >> 5;
    if (node >= N) return;
    int lane = threadIdx.x & 31;
    const unsigned* base = (const unsigned*)hs;

    int beg = g_start[node], cnt = g_cnt[node];
    float a[2] = {0.f, 0.f};
    acch2(a, base[(size_t)node * 32 + lane], 1.f);   // self loop (already scaled)

    int e = 0;
    for (; e + 8 <= cnt; e += 8) {
        int s0 = g_csr[beg+e  ], s1 = g_csr[beg+e+1], s2 = g_csr[beg+e+2], s3 = g_csr[beg+e+3];
        int s4 = g_csr[beg+e+4], s5 = g_csr[beg+e+5], s6 = g_csr[beg+e+6], s7 = g_csr[beg+e+7];
        unsigned v0 = base[(size_t)s0*32+lane], v1 = base[(size_t)s1*32+lane];
        unsigned v2 = base[(size_t)s2*32+lane], v3 = base[(size_t)s3*32+lane];
        unsigned v4 = base[(size_t)s4*32+lane], v5 = base[(size_t)s5*32+lane];
        unsigned v6 = base[(size_t)s6*32+lane], v7 = base[(size_t)s7*32+lane];
        acch2(a, v0, 1.f); acch2(a, v1, 1.f); acch2(a, v2, 1.f); acch2(a, v3, 1.f);
        acch2(a, v4, 1.f); acch2(a, v5, 1.f); acch2(a, v6, 1.f); acch2(a, v7, 1.f);
    }
    for (; e < cnt; e++)
        acch2(a, base[(size_t)g_csr[beg+e]*32+lane], 1.f);

    float dw = g_dis[node];
    float2 b = ((const float2*)bias)[lane];
    float2 r;
    r.x = fmaf(dw, a[0], b.x);
    r.y = fmaf(dw, a[1], b.y);
    ((float2*)out)[(size_t)node * 32 + lane] = r;
}

// ---------------- launch ----------------
extern "C" void kernel_launch(void* const* d_in, const int* in_sizes, int n_in,
                              void* d_out, int out_size)
{
    const float* x   = (const float*)d_in[0];
    const void*  ei  = d_in[1];
    const float* W1  = (const float*)d_in[2];
    const float* b1  = (const float*)d_in[3];
    const float* W2  = (const float*)d_in[4];
    const float* b2  = (const float*)d_in[5];
    float*       out = (float*)d_out;

    const int N = in_sizes[0] / IN_C;   // 50000
    const int E = in_sizes[1] / 2;      // 800000
    const int nscan = (N + SCAN_B - 1) / SCAN_B;
    const int e4blocks = ((E + 3) / 4 + 255) / 256;

    __half *p_hs1, *p_act1, *p_hs2;
    int    *p_cnt;
    unsigned long long* p_desc;
    cudaGetSymbolAddress((void**)&p_hs1,  g_hs1);
    cudaGetSymbolAddress((void**)&p_act1, g_act1);
    cudaGetSymbolAddress((void**)&p_hs2,  g_hs2);
    cudaGetSymbolAddress((void**)&p_cnt,  g_cnt);
    cudaGetSymbolAddress((void**)&p_desc, g_desc);

    static cudaStream_t s2 = nullptr;
    static cudaEvent_t evFork = nullptr, evJoin = nullptr;
    if (!s2) {
        if (cudaStreamCreateWithFlags(&s2, cudaStreamNonBlocking) != cudaSuccess) s2 = nullptr;
        if (s2) {
            cudaEventCreateWithFlags(&evFork, cudaEventDisableTiming);
            cudaEventCreateWithFlags(&evJoin, cudaEventDisableTiming);
        }
    }

    // ---- fork: GEMM1 (split-bf16) on side stream, overlapping CSR build ----
    bool forked = false;
    if (s2) {
        cudaEventRecord(evFork, 0);
        cudaStreamWaitEvent(s2, evFork, 0);
        gemm16<HID, false, false><<<(N + 127) / 128, 256, 0, s2>>>(x, W1, p_hs1, N, IN_C);
        cudaEventRecord(evJoin, s2);
        forked = true;
    }

    // ---- main stream: CSR build + dis (3 dependent kernels) ----
    cudaMemsetAsync(p_cnt,  0, (size_t)N * sizeof(int), 0);
    cudaMemsetAsync(p_desc, 0, (size_t)nscan * sizeof(unsigned long long), 0);
    k_hist<<<e4blocks, 256>>>(ei, E);
    k_scan<<<nscan, SCAN_B>>>(N);
    k_fill<<<e4blocks, 256>>>(ei, E);

    if (forked) cudaStreamWaitEvent(0, evJoin, 0);
    else        gemm16<HID, false, false><<<(N + 127) / 128, 256>>>(x, W1, p_hs1, N, IN_C);

    // ---- layer 1 aggregate (+dis both sides, bias, relu) -> f16 act1 ----
    k_agg128<<<(N * 32 + 255) / 256, 256>>>(p_hs1, p_act1, b1, N);

    // ---- layer 2 GEMM (f16 A exact, W2 f16-split, dis-scaled) + aggregate ----
    gemm16<OUTC, true, true><<<(N + 127) / 128, 256>>>(p_act1, W2, p_hs2, N, HID);
    k_agg64<<<(N * 32 + 255) / 256, 256>>>(p_hs2, out, b2, N);
}